// round 5
// baseline (speedup 1.0000x reference)
#include <cuda_runtime.h>
#include <cstdint>
#include <cfloat>

#define NMAX 250000
#define EMAX 4000000
#define HID  16
#define NBIN 17   // 16 thresholds -> 17 intervals

// ---- scratch (static __device__ globals) ----
__device__ int    d_degi[NMAX];
__device__ float  d_q[NMAX];        // dinv*x
__device__ float  d_s1raw[NMAX];
__device__ __align__(16) float2 d_g[NMAX];    // {dinv, s1}
__device__ __align__(16) float4 d_nd[NMAX];   // {a=dinv*s1, d=dinv, j(bits), 0}
__device__ __align__(16) float2 d_bins[NBIN * NMAX];  // [j][node] -> {sumA, sumD}, 34MB
__device__ float  d_t[HID];         // thresholds
__device__ int    d_r[HID];         // rank_k = #{k': t_k' < t_k}

// ---------------- kernels ----------------

// tiny: zero deg (int) + s1raw
__global__ void k_zero(int n) {
    int i = blockIdx.x * blockDim.x + threadIdx.x;
    if (i < n) { d_degi[i] = 0; d_s1raw[i] = 0.0f; }
}

// fused: zero bins (grid-stride float4) + thresholds + degree count (8 edges/thread)
__global__ void k_deg(const int* __restrict__ ei,
                      const float* __restrict__ W1, const float* __restrict__ b1,
                      int E, int n) {
    int tid = blockIdx.x * blockDim.x + threadIdx.x;
    int nthr = gridDim.x * blockDim.x;

    float4* b4 = reinterpret_cast<float4*>(d_bins);
    const int NB4 = NBIN * NMAX / 2;
    for (int i = tid; i < NB4; i += nthr)
        b4[i] = make_float4(0.f, 0.f, 0.f, 0.f);

    if (tid == 0) {
        float t[HID];
        for (int k = 0; k < HID; k++) {
            float w = W1[k], b = b1[k];
            t[k] = (w != 0.0f) ? (-b / w) : -FLT_MAX;
            d_t[k] = t[k];
        }
        for (int k = 0; k < HID; k++) {
            int r = 0;
            for (int k2 = 0; k2 < HID; k2++) r += (t[k2] < t[k]);
            d_r[k] = r;
        }
    }

    const int* col = ei + E;
    if ((E & 7) == 0) {
        int base = tid * 8;
        if (base < E) {
            int4 ca = *reinterpret_cast<const int4*>(col + base);
            int4 cb = *reinterpret_cast<const int4*>(col + base + 4);
            int c[8] = {ca.x, ca.y, ca.z, ca.w, cb.x, cb.y, cb.z, cb.w};
#pragma unroll
            for (int u = 0; u < 8; u++)
                if ((unsigned)c[u] < (unsigned)n) atomicAdd(d_degi + c[u], 1);
        }
    } else {
        for (int e = tid; e < E; e += nthr) {
            int c = col[e];
            if ((unsigned)c < (unsigned)n) atomicAdd(d_degi + c, 1);
        }
    }
}

// dinv = rsqrt(deg+1); q = dinv*x
__global__ void k_node1(const float* __restrict__ x, int n) {
    int i = blockIdx.x * blockDim.x + threadIdx.x;
    if (i < n) {
        float di = rsqrtf((float)(d_degi[i] + 1));   // +1 = self-loop
        d_q[i] = di * x[i];
        d_g[i].x = di;
    }
}

// s1raw[col] += q[row], 8 edges/thread
__global__ void k_edge1(const int* __restrict__ ei, int E, int n) {
    int tid = blockIdx.x * blockDim.x + threadIdx.x;
    const int* col = ei + E;
    if ((E & 7) == 0) {
        int base = tid * 8;
        if (base >= E) return;
        int4 ra = *reinterpret_cast<const int4*>(ei + base);
        int4 rb = *reinterpret_cast<const int4*>(ei + base + 4);
        int4 ca = *reinterpret_cast<const int4*>(col + base);
        int4 cb = *reinterpret_cast<const int4*>(col + base + 4);
        int r[8] = {ra.x, ra.y, ra.z, ra.w, rb.x, rb.y, rb.z, rb.w};
        int c[8] = {ca.x, ca.y, ca.z, ca.w, cb.x, cb.y, cb.z, cb.w};
        float q[8];
#pragma unroll
        for (int u = 0; u < 8; u++)
            q[u] = ((unsigned)r[u] < (unsigned)n) ? __ldg(d_q + r[u]) : 0.0f;
#pragma unroll
        for (int u = 0; u < 8; u++)
            if ((unsigned)c[u] < (unsigned)n) atomicAdd(d_s1raw + c[u], q[u]);
    } else {
        int nthr = gridDim.x * blockDim.x;
        for (int e = tid; e < E; e += nthr) {
            int r = ei[e], c = col[e];
            if ((unsigned)r < (unsigned)n && (unsigned)c < (unsigned)n)
                atomicAdd(d_s1raw + c, __ldg(d_q + r));
        }
    }
}

// s1 = dinv*(s1raw + q); pack nd = {dinv*s1, dinv, j}
__global__ void k_node2(int n) {
    __shared__ float st[HID];
    if (threadIdx.x < HID) st[threadIdx.x] = d_t[threadIdx.x];
    __syncthreads();
    int i = blockIdx.x * blockDim.x + threadIdx.x;
    if (i < n) {
        float di = d_g[i].x;
        float s1 = di * (d_s1raw[i] + d_q[i]);
        d_g[i] = make_float2(di, s1);
        int j = 0;
#pragma unroll
        for (int k = 0; k < HID; k++) j += (st[k] < s1);
        d_nd[i] = make_float4(di * s1, di, __int_as_float(j), 0.0f);
    }
}

// layer-2 binned scatter: bins[j(row)][col] += {a_row, d_row}, 8 edges/thread
__global__ void k_edge2(const int* __restrict__ ei, int E, int n) {
    int tid = blockIdx.x * blockDim.x + threadIdx.x;
    const int* col = ei + E;
    if ((E & 7) == 0) {
        int base = tid * 8;
        if (base >= E) return;
        int4 ra = *reinterpret_cast<const int4*>(ei + base);
        int4 rb = *reinterpret_cast<const int4*>(ei + base + 4);
        int4 ca = *reinterpret_cast<const int4*>(col + base);
        int4 cb = *reinterpret_cast<const int4*>(col + base + 4);
        int r[8] = {ra.x, ra.y, ra.z, ra.w, rb.x, rb.y, rb.z, rb.w};
        int c[8] = {ca.x, ca.y, ca.z, ca.w, cb.x, cb.y, cb.z, cb.w};
        float4 nd[8];
#pragma unroll
        for (int u = 0; u < 8; u++)
            nd[u] = ((unsigned)r[u] < (unsigned)n) ? __ldg(d_nd + r[u])
                                                   : make_float4(0.f, 0.f, 0.f, 0.f);
#pragma unroll
        for (int u = 0; u < 8; u++) {
            if ((unsigned)c[u] < (unsigned)n) {
                int j = __float_as_int(nd[u].z);
                float2* dst = d_bins + (size_t)j * NMAX + c[u];
                asm volatile("red.global.add.v2.f32 [%0], {%1, %2};"
                             :: "l"(dst), "f"(nd[u].x), "f"(nd[u].y) : "memory");
            }
        }
    } else {
        int nthr = gridDim.x * blockDim.x;
        for (int e = tid; e < E; e += nthr) {
            int r = ei[e], c = col[e];
            if ((unsigned)r < (unsigned)n && (unsigned)c < (unsigned)n) {
                float4 nd = __ldg(d_nd + r);
                int j = __float_as_int(nd.z);
                float2* dst = d_bins + (size_t)j * NMAX + c;
                asm volatile("red.global.add.v2.f32 [%0], {%1, %2};"
                             :: "l"(dst), "f"(nd.x), "f"(nd.y) : "memory");
            }
        }
    }
}

// fused epilogue: reconstruct agg2 from bins, self-loop, dinv, W2+relu, Wfc -> out
__global__ void k_out(const float* __restrict__ W1, const float* __restrict__ b1,
                      const float* __restrict__ W2, const float* __restrict__ b2,
                      const float* __restrict__ Wfc, const float* __restrict__ bfc,
                      float* __restrict__ out, int n) {
    __shared__ float sW2[HID * HID], sWfc[HID * 4];
    __shared__ float sw1[HID], sb1[HID], sb2[HID], sbfc[4];
    __shared__ int   sr[HID];
    int t = threadIdx.x;
    if (t < HID * HID) sW2[t] = W2[t];
    if (t < HID * 4)   sWfc[t] = Wfc[t];
    if (t < HID) { sw1[t] = W1[t]; sb1[t] = b1[t]; sb2[t] = b2[t]; sr[t] = d_r[t]; }
    if (t < 4)   sbfc[t] = bfc[t];
    __syncthreads();

    int i = blockIdx.x * blockDim.x + t;
    if (i >= n) return;

    float aa[NBIN], dd[NBIN];
    float TD = 0.f;
#pragma unroll
    for (int j = 0; j < NBIN; j++) {
        float2 b = __ldg(d_bins + (size_t)j * NMAX + i);
        aa[j] = b.x; dd[j] = b.y;
        TD += b.y;
    }
    float2 gi = d_g[i];
    float di = gi.x, s1 = gi.y;

    float afull[HID];
#pragma unroll
    for (int k = 0; k < HID; k++) {
        float wk = sw1[k], bk = sb1[k];
        int   rk = sr[k];
        float A = 0.f, D = 0.f;
        if (wk > 0.f) {
#pragma unroll
            for (int j = 0; j < NBIN; j++) if (j > rk) { A += aa[j]; D += dd[j]; }
        } else if (wk < 0.f) {
#pragma unroll
            for (int j = 0; j < NBIN; j++) if (j <= rk) { A += aa[j]; D += dd[j]; }
        } else {
            A = 0.f; D = (bk > 0.f) ? TD : 0.f;
        }
        float agg = fmaf(wk, A, bk * D);                 // sum over real edges
        float h1c = fmaxf(fmaf(s1, wk, bk), 0.f);        // self-loop message
        afull[k] = di * fmaf(di, h1c, agg);
    }
    float h2[HID];
#pragma unroll
    for (int j = 0; j < HID; j++) {
        float acc = sb2[j];
#pragma unroll
        for (int k = 0; k < HID; k++) acc = fmaf(afull[k], sW2[k * HID + j], acc);
        h2[j] = fmaxf(acc, 0.f);
    }
#pragma unroll
    for (int j = 0; j < 4; j++) {
        float acc = sbfc[j];
#pragma unroll
        for (int k = 0; k < HID; k++) acc = fmaf(h2[k], sWfc[k * 4 + j], acc);
        out[(size_t)i * 4 + j] = acc;
    }
}

// ---------------- launch ----------------

extern "C" void kernel_launch(void* const* d_in, const int* in_sizes, int n_in,
                              void* d_out, int out_size) {
    const float* x   = (const float*)d_in[0];
    const int*   ei  = (const int*)d_in[1];     // int32 (JAX x64 disabled)
    const float* W1  = (const float*)d_in[2];
    const float* b1  = (const float*)d_in[3];
    const float* W2  = (const float*)d_in[4];
    const float* b2  = (const float*)d_in[5];
    const float* Wfc = (const float*)d_in[6];
    const float* bfc = (const float*)d_in[7];
    float* out = (float*)d_out;

    int n = in_sizes[0];
    int E = in_sizes[1] / 2;

    const int T = 256;
    int nb_nodes = (n + T - 1) / T;
    int nb_edge8;
    if ((E & 7) == 0) nb_edge8 = (E / 8 + T - 1) / T;
    else              nb_edge8 = (E + T - 1) / T > 8192 ? 8192 : (E + T - 1) / T;

    k_zero <<<nb_nodes, T>>>(n);
    k_deg  <<<nb_edge8, T>>>(ei, W1, b1, E, n);
    k_node1<<<nb_nodes, T>>>(x, n);
    k_edge1<<<nb_edge8, T>>>(ei, E, n);
    k_node2<<<nb_nodes, T>>>(n);
    k_edge2<<<nb_edge8, T>>>(ei, E, n);
    k_out  <<<nb_nodes, T>>>(W1, b1, W2, b2, Wfc, bfc, out, n);
}

// round 6
// speedup vs baseline: 1.1106x; 1.1106x over previous
#include <cuda_runtime.h>
#include <cstdint>
#include <cfloat>

#define NMAX 250000
#define EMAX 4000000
#define HID  16
#define NBIN 17   // 16 thresholds -> 17 intervals

// ---- scratch (static __device__ globals) ----
__device__ int    d_degi[NMAX];
__device__ float  d_q[NMAX];        // dinv*x
__device__ float  d_s1raw[NMAX];
__device__ __align__(16) float2 d_g[NMAX];    // {dinv, s1}
__device__ __align__(16) float2 d_nd[NMAX];   // {a=dinv*s1, dinv with j in low 5 mantissa bits}
__device__ __align__(16) float2 d_bins[NBIN * NMAX];  // [j][node] -> {sumA, sumD}, 34MB
__device__ float  d_t[HID];         // thresholds
__device__ int    d_r[HID];         // rank_k = #{k': t_k' < t_k}

// ---------------- kernels ----------------

// tiny: zero deg (int) + s1raw
__global__ void k_zero(int n) {
    int i = blockIdx.x * blockDim.x + threadIdx.x;
    if (i < n) { d_degi[i] = 0; d_s1raw[i] = 0.0f; }
}

// fused: zero bins (grid-stride float4) + thresholds + degree count (1 edge/thread)
__global__ void k_deg(const int* __restrict__ ei,
                      const float* __restrict__ W1, const float* __restrict__ b1,
                      int E, int n) {
    int tid = blockIdx.x * blockDim.x + threadIdx.x;
    int nthr = gridDim.x * blockDim.x;

    float4* b4 = reinterpret_cast<float4*>(d_bins);
    const int NB4 = NBIN * NMAX / 2;
    for (int i = tid; i < NB4; i += nthr)
        b4[i] = make_float4(0.f, 0.f, 0.f, 0.f);

    if (tid == 0) {
        float t[HID];
        for (int k = 0; k < HID; k++) {
            float w = W1[k], b = b1[k];
            t[k] = (w != 0.0f) ? (-b / w) : -FLT_MAX;
            d_t[k] = t[k];
        }
        for (int k = 0; k < HID; k++) {
            int r = 0;
            for (int k2 = 0; k2 < HID; k2++) r += (t[k2] < t[k]);
            d_r[k] = r;
        }
    }

    const int* col = ei + E;
    for (int e = tid; e < E; e += nthr) {
        int c = col[e];
        if ((unsigned)c < (unsigned)n)
            atomicAdd(d_degi + c, 1);
    }
}

// dinv = rsqrt(deg+1); q = dinv*x
__global__ void k_node1(const float* __restrict__ x, int n) {
    int i = blockIdx.x * blockDim.x + threadIdx.x;
    if (i < n) {
        float di = rsqrtf((float)(d_degi[i] + 1));   // +1 = self-loop
        d_q[i] = di * x[i];
        d_g[i].x = di;
    }
}

// s1raw[col] += q[row], 1 edge/thread
__global__ void k_edge1(const int* __restrict__ ei, int E, int n) {
    int e = blockIdx.x * blockDim.x + threadIdx.x;
    if (e < E) {
        int r = ei[e];
        int c = ei[E + e];
        if ((unsigned)r < (unsigned)n && (unsigned)c < (unsigned)n)
            atomicAdd(d_s1raw + c, __ldg(d_q + r));
    }
}

// s1 = dinv*(s1raw + q); pack nd = {dinv*s1, dinv|j}
__global__ void k_node2(int n) {
    __shared__ float st[HID];
    if (threadIdx.x < HID) st[threadIdx.x] = d_t[threadIdx.x];
    __syncthreads();
    int i = blockIdx.x * blockDim.x + threadIdx.x;
    if (i < n) {
        float di = d_g[i].x;
        float s1 = di * (d_s1raw[i] + d_q[i]);
        d_g[i] = make_float2(di, s1);
        int j = 0;
#pragma unroll
        for (int k = 0; k < HID; k++) j += (st[k] < s1);
        uint32_t db = (__float_as_uint(di) & ~31u) | (uint32_t)j;  // j in low 5 mantissa bits
        d_nd[i] = make_float2(di * s1, __uint_as_float(db));
    }
}

// layer-2 binned scatter: bins[j(row)][col] += {a_row, d_row}, 1 edge/thread
__global__ void k_edge2(const int* __restrict__ ei, int E, int n) {
    int e = blockIdx.x * blockDim.x + threadIdx.x;
    if (e < E) {
        int r = ei[e];
        int c = ei[E + e];
        if ((unsigned)r < (unsigned)n && (unsigned)c < (unsigned)n) {
            float2 nd = __ldg(d_nd + r);
            uint32_t db = __float_as_uint(nd.y);
            int j = (int)(db & 31u);
            float d = __uint_as_float(db & ~31u);
            float2* dst = d_bins + (size_t)j * NMAX + c;
            asm volatile("red.global.add.v2.f32 [%0], {%1, %2};"
                         :: "l"(dst), "f"(nd.x), "f"(d) : "memory");
        }
    }
}

// fused epilogue: reconstruct agg2 from bins, self-loop, dinv, W2+relu, Wfc -> out
__global__ void k_out(const float* __restrict__ W1, const float* __restrict__ b1,
                      const float* __restrict__ W2, const float* __restrict__ b2,
                      const float* __restrict__ Wfc, const float* __restrict__ bfc,
                      float* __restrict__ out, int n) {
    __shared__ float sW2[HID * HID], sWfc[HID * 4];
    __shared__ float sw1[HID], sb1[HID], sb2[HID], sbfc[4];
    __shared__ int   sr[HID];
    int t = threadIdx.x;
    if (t < HID * HID) sW2[t] = W2[t];
    if (t < HID * 4)   sWfc[t] = Wfc[t];
    if (t < HID) { sw1[t] = W1[t]; sb1[t] = b1[t]; sb2[t] = b2[t]; sr[t] = d_r[t]; }
    if (t < 4)   sbfc[t] = bfc[t];
    __syncthreads();

    int i = blockIdx.x * blockDim.x + t;
    if (i >= n) return;

    float aa[NBIN], dd[NBIN];
    float TD = 0.f;
#pragma unroll
    for (int j = 0; j < NBIN; j++) {
        float2 b = __ldg(d_bins + (size_t)j * NMAX + i);
        aa[j] = b.x; dd[j] = b.y;
        TD += b.y;
    }
    float2 gi = d_g[i];
    float di = gi.x, s1 = gi.y;

    float afull[HID];
#pragma unroll
    for (int k = 0; k < HID; k++) {
        float wk = sw1[k], bk = sb1[k];
        int   rk = sr[k];
        float A = 0.f, D = 0.f;
        if (wk > 0.f) {
#pragma unroll
            for (int j = 0; j < NBIN; j++) if (j > rk) { A += aa[j]; D += dd[j]; }
        } else if (wk < 0.f) {
#pragma unroll
            for (int j = 0; j < NBIN; j++) if (j <= rk) { A += aa[j]; D += dd[j]; }
        } else {
            A = 0.f; D = (bk > 0.f) ? TD : 0.f;
        }
        float agg = fmaf(wk, A, bk * D);                 // sum over real edges
        float h1c = fmaxf(fmaf(s1, wk, bk), 0.f);        // self-loop message
        afull[k] = di * fmaf(di, h1c, agg);
    }
    float h2[HID];
#pragma unroll
    for (int j = 0; j < HID; j++) {
        float acc = sb2[j];
#pragma unroll
        for (int k = 0; k < HID; k++) acc = fmaf(afull[k], sW2[k * HID + j], acc);
        h2[j] = fmaxf(acc, 0.f);
    }
#pragma unroll
    for (int j = 0; j < 4; j++) {
        float acc = sbfc[j];
#pragma unroll
        for (int k = 0; k < HID; k++) acc = fmaf(h2[k], sWfc[k * 4 + j], acc);
        out[(size_t)i * 4 + j] = acc;
    }
}

// ---------------- launch ----------------

extern "C" void kernel_launch(void* const* d_in, const int* in_sizes, int n_in,
                              void* d_out, int out_size) {
    const float* x   = (const float*)d_in[0];
    const int*   ei  = (const int*)d_in[1];     // int32 (JAX x64 disabled)
    const float* W1  = (const float*)d_in[2];
    const float* b1  = (const float*)d_in[3];
    const float* W2  = (const float*)d_in[4];
    const float* b2  = (const float*)d_in[5];
    const float* Wfc = (const float*)d_in[6];
    const float* bfc = (const float*)d_in[7];
    float* out = (float*)d_out;

    int n = in_sizes[0];
    int E = in_sizes[1] / 2;

    const int T = 256;
    int nb_nodes = (n + T - 1) / T;
    int nb_edges = (E + T - 1) / T;

    k_zero <<<nb_nodes, T>>>(n);
    k_deg  <<<nb_edges, T>>>(ei, W1, b1, E, n);
    k_node1<<<nb_nodes, T>>>(x, n);
    k_edge1<<<nb_edges, T>>>(ei, E, n);
    k_node2<<<nb_nodes, T>>>(n);
    k_edge2<<<nb_edges, T>>>(ei, E, n);
    k_out  <<<nb_nodes, T>>>(W1, b1, W2, b2, Wfc, bfc, out, n);
}

// round 7
// speedup vs baseline: 1.1132x; 1.0023x over previous
#include <cuda_runtime.h>
#include <cstdint>
#include <cfloat>

#define NMAX 250000
#define EMAX 4000000
#define HID  16
#define NBIN 17   // 16 thresholds -> 17 intervals

// ---- scratch (static __device__ globals) ----
__device__ int    d_degi[NMAX];
__device__ float  d_q[NMAX];        // dinv*x
__device__ float  d_s1raw[NMAX];
__device__ __align__(16) float2 d_g[NMAX];    // {dinv, s1}
__device__ __align__(16) float2 d_nd[NMAX];   // {a=dinv*s1, dinv with j in low 5 mantissa bits}
__device__ __align__(16) float2 d_bins[NBIN * NMAX];  // [j][node] -> {sumA, sumD}, 34MB
__device__ float  d_t[HID];         // thresholds
__device__ int    d_r[HID];         // rank_k = #{k': t_k' < t_k}

// ---------------- kernels ----------------

// streaming zero of bins + deg + s1raw; thread 0 computes thresholds + ranks
__global__ void k_zero(const float* __restrict__ W1, const float* __restrict__ b1, int n) {
    int tid = blockIdx.x * blockDim.x + threadIdx.x;
    int nthr = gridDim.x * blockDim.x;

    float4* b4 = reinterpret_cast<float4*>(d_bins);
    const int NB4 = NBIN * NMAX / 2;
    for (int i = tid; i < NB4; i += nthr)
        b4[i] = make_float4(0.f, 0.f, 0.f, 0.f);
    if (tid < n) { d_degi[tid] = 0; d_s1raw[tid] = 0.0f; }

    if (tid == 0) {
        float t[HID];
        for (int k = 0; k < HID; k++) {
            float w = W1[k], b = b1[k];
            t[k] = (w != 0.0f) ? (-b / w) : -FLT_MAX;
            d_t[k] = t[k];
        }
        for (int k = 0; k < HID; k++) {
            int r = 0;
            for (int k2 = 0; k2 < HID; k2++) r += (t[k2] < t[k]);
            d_r[k] = r;
        }
    }
}

// pure degree count: deg[col]++
__global__ void k_deg(const int* __restrict__ ei, int E) {
    int e = blockIdx.x * blockDim.x + threadIdx.x;
    if (e < E)
        atomicAdd(d_degi + ei[E + e], 1);
}

// dinv = rsqrt(deg+1); q = dinv*x
__global__ void k_node1(const float* __restrict__ x, int n) {
    int i = blockIdx.x * blockDim.x + threadIdx.x;
    if (i < n) {
        float di = rsqrtf((float)(d_degi[i] + 1));   // +1 = self-loop
        d_q[i] = di * x[i];
        d_g[i].x = di;
    }
}

// s1raw[col] += q[row]
__global__ void k_edge1(const int* __restrict__ ei, int E) {
    int e = blockIdx.x * blockDim.x + threadIdx.x;
    if (e < E) {
        int r = ei[e];
        int c = ei[E + e];
        atomicAdd(d_s1raw + c, __ldg(d_q + r));
    }
}

// s1 = dinv*(s1raw + q); pack nd = {dinv*s1, dinv|j}
__global__ void k_node2(int n) {
    __shared__ float st[HID];
    if (threadIdx.x < HID) st[threadIdx.x] = d_t[threadIdx.x];
    __syncthreads();
    int i = blockIdx.x * blockDim.x + threadIdx.x;
    if (i < n) {
        float di = d_g[i].x;
        float s1 = di * (d_s1raw[i] + d_q[i]);
        d_g[i] = make_float2(di, s1);
        int j = 0;
#pragma unroll
        for (int k = 0; k < HID; k++) j += (st[k] < s1);
        uint32_t db = (__float_as_uint(di) & ~31u) | (uint32_t)j;  // j in low 5 mantissa bits
        d_nd[i] = make_float2(di * s1, __uint_as_float(db));
    }
}

// layer-2 binned scatter: bins[j(row)][col] += {a_row, d_row}
__global__ void k_edge2(const int* __restrict__ ei, int E) {
    int e = blockIdx.x * blockDim.x + threadIdx.x;
    if (e < E) {
        int r = ei[e];
        int c = ei[E + e];
        float2 nd = __ldg(d_nd + r);
        uint32_t db = __float_as_uint(nd.y);
        int j = (int)(db & 31u);
        float d = __uint_as_float(db & ~31u);
        float2* dst = d_bins + (size_t)j * NMAX + c;
        asm volatile("red.global.add.v2.f32 [%0], {%1, %2};"
                     :: "l"(dst), "f"(nd.x), "f"(d) : "memory");
    }
}

// fused epilogue: reconstruct agg2 from bins, self-loop, dinv, W2+relu, Wfc -> out
__global__ void k_out(const float* __restrict__ W1, const float* __restrict__ b1,
                      const float* __restrict__ W2, const float* __restrict__ b2,
                      const float* __restrict__ Wfc, const float* __restrict__ bfc,
                      float* __restrict__ out, int n) {
    __shared__ float sW2[HID * HID], sWfc[HID * 4];
    __shared__ float sw1[HID], sb1[HID], sb2[HID], sbfc[4];
    __shared__ int   sr[HID];
    int t = threadIdx.x;
    if (t < HID * HID) sW2[t] = W2[t];
    if (t < HID * 4)   sWfc[t] = Wfc[t];
    if (t < HID) { sw1[t] = W1[t]; sb1[t] = b1[t]; sb2[t] = b2[t]; sr[t] = d_r[t]; }
    if (t < 4)   sbfc[t] = bfc[t];
    __syncthreads();

    int i = blockIdx.x * blockDim.x + t;
    if (i >= n) return;

    float aa[NBIN], dd[NBIN];
    float TD = 0.f;
#pragma unroll
    for (int j = 0; j < NBIN; j++) {
        float2 b = __ldg(d_bins + (size_t)j * NMAX + i);
        aa[j] = b.x; dd[j] = b.y;
        TD += b.y;
    }
    float2 gi = d_g[i];
    float di = gi.x, s1 = gi.y;

    float afull[HID];
#pragma unroll
    for (int k = 0; k < HID; k++) {
        float wk = sw1[k], bk = sb1[k];
        int   rk = sr[k];
        float A = 0.f, D = 0.f;
        if (wk > 0.f) {
#pragma unroll
            for (int j = 0; j < NBIN; j++) if (j > rk) { A += aa[j]; D += dd[j]; }
        } else if (wk < 0.f) {
#pragma unroll
            for (int j = 0; j < NBIN; j++) if (j <= rk) { A += aa[j]; D += dd[j]; }
        } else {
            A = 0.f; D = (bk > 0.f) ? TD : 0.f;
        }
        float agg = fmaf(wk, A, bk * D);                 // sum over real edges
        float h1c = fmaxf(fmaf(s1, wk, bk), 0.f);        // self-loop message
        afull[k] = di * fmaf(di, h1c, agg);
    }
    float h2[HID];
#pragma unroll
    for (int j = 0; j < HID; j++) {
        float acc = sb2[j];
#pragma unroll
        for (int k = 0; k < HID; k++) acc = fmaf(afull[k], sW2[k * HID + j], acc);
        h2[j] = fmaxf(acc, 0.f);
    }
#pragma unroll
    for (int j = 0; j < 4; j++) {
        float acc = sbfc[j];
#pragma unroll
        for (int k = 0; k < HID; k++) acc = fmaf(h2[k], sWfc[k * 4 + j], acc);
        out[(size_t)i * 4 + j] = acc;
    }
}

// ---------------- launch ----------------

extern "C" void kernel_launch(void* const* d_in, const int* in_sizes, int n_in,
                              void* d_out, int out_size) {
    const float* x   = (const float*)d_in[0];
    const int*   ei  = (const int*)d_in[1];     // int32 (JAX x64 disabled)
    const float* W1  = (const float*)d_in[2];
    const float* b1  = (const float*)d_in[3];
    const float* W2  = (const float*)d_in[4];
    const float* b2  = (const float*)d_in[5];
    const float* Wfc = (const float*)d_in[6];
    const float* bfc = (const float*)d_in[7];
    float* out = (float*)d_out;

    int n = in_sizes[0];
    int E = in_sizes[1] / 2;

    const int T = 256;
    int nb_nodes = (n + T - 1) / T;
    int nb_edges = (E + T - 1) / T;
    const int NB4 = NBIN * NMAX / 2;
    int nb_zero  = (NB4 + T - 1) / T;           // covers bins; tid<n covers deg/s1raw

    k_zero <<<nb_zero,  T>>>(W1, b1, n);
    k_deg  <<<nb_edges, T>>>(ei, E);
    k_node1<<<nb_nodes, T>>>(x, n);
    k_edge1<<<nb_edges, T>>>(ei, E);
    k_node2<<<nb_nodes, T>>>(n);
    k_edge2<<<nb_edges, T>>>(ei, E);
    k_out  <<<nb_nodes, T>>>(W1, b1, W2, b2, Wfc, bfc, out, n);
}